// round 4
// baseline (speedup 1.0000x reference)
#include <cuda_runtime.h>

// ---------------------------------------------------------------------------
// SSIM (16,3,512,512) fp32, 11x11 gaussian (sigma=1.5), zero padding.
// Round-4:
//  * grid 1536 blocks (48 planes x 4 col-strips x 8 row-bands of 64) --
//    previous grid capped occupancy at ~20 warps/SM (latency-bound).
//  * 4-quantity ring (wa, wb, w(a^2+b^2), w(ab)) -- s11/s22 only ever used
//    summed, saves 11 ring registers and 11 FMAs/pixel.
//  * per-column (a^2+b^2, a*b) precomputed at load time into smem (hoists
//    redundant products out of the 11-tap horizontal loop).
//  * __launch_bounds__(128, 8) -> <=64 regs -> 32 warps/SM.
// ---------------------------------------------------------------------------

#define IMG_H 512
#define IMG_W 512
#define N_PLANES 48
#define N_BLOCKS (48 * 4 * 8)
#define TOTAL_PIX 12582912.0

#define GW0 0.26601172f
#define GW1 0.21300554f
#define GW2 0.10936069f
#define GW3 0.03600077f
#define GW4 0.00759876f
#define GW5 0.00102842f

__device__ double g_acc;
__device__ unsigned int g_count;

typedef unsigned long long u64;

__device__ __forceinline__ u64 pk2(float lo, float hi) {
    u64 r; asm("mov.b64 %0, {%1, %2};" : "=l"(r) : "f"(lo), "f"(hi)); return r;
}
__device__ __forceinline__ float2 upk2(u64 v) {
    float2 r; asm("mov.b64 {%0, %1}, %2;" : "=f"(r.x), "=f"(r.y) : "l"(v)); return r;
}

__global__ __launch_bounds__(128, 8)
void ssim_kernel(const float* __restrict__ img1, const float* __restrict__ img2,
                 float* __restrict__ out) {
    const float GWs[11] = {GW5, GW4, GW3, GW2, GW1, GW0, GW1, GW2, GW3, GW4, GW5};

    const int plane = blockIdx.x;     // 0..47
    const int strip = blockIdx.y;     // 0..3   (column strips of 128)
    const int band  = blockIdx.z;     // 0..7   (row bands of 64)
    const int tx    = threadIdx.x;    // 0..127

    const int col0 = strip * 128;
    const int row0 = band * 64;

    const float* __restrict__ p1 = img1 + (size_t)plane * (IMG_H * IMG_W);
    const float* __restrict__ p2 = img2 + (size_t)plane * (IMG_H * IMG_W);

    // sab: interleaved (a,b); sq: interleaved (a^2+b^2, a*b)
    __shared__ u64 sab[11][139];
    __shared__ u64 sq [11][139];

    // ring: 4 quantities per row slot
    float r0[11], r1[11], r2[11], r3[11];
#pragma unroll
    for (int k = 0; k < 11; ++k) { r0[k] = 0.f; r1[k] = 0.f; r2[k] = 0.f; r3[k] = 0.f; }

    float acc = 0.f;

    const float C1  = 1e-4f;
    const float C2  = 9e-4f;
    const float C2E = 9e-4f + 1e-6f;

    const int c0 = col0 - 5 + tx;
    const bool colok0 = ((unsigned)c0 < (unsigned)IMG_W);
    const int c1 = c0 + 128;
    const bool colok1 = ((unsigned)c1 < (unsigned)IMG_W);

    // input rows y = row0 - 5 + n, n = t*11 + k; emit output for n in [10, 74)
    for (int t = 0; t < 7; ++t) {
        const int base = row0 - 5 + t * 11;

        __syncthreads();
#pragma unroll
        for (int r = 0; r < 11; ++r) {
            const int y = base + r;
            const bool rowok = ((unsigned)y < (unsigned)IMG_H);
            const float* q1 = p1 + y * IMG_W;
            const float* q2 = p2 + y * IMG_W;
            const bool ok0 = rowok && colok0;
            const float a = ok0 ? __ldg(q1 + c0) : 0.f;
            const float b = ok0 ? __ldg(q2 + c0) : 0.f;
            sab[r][tx] = pk2(a, b);
            sq [r][tx] = pk2(fmaf(b, b, a * a), a * b);
            if (tx < 11) {
                const bool ok1 = rowok && colok1;
                const float a1 = ok1 ? __ldg(q1 + c1) : 0.f;
                const float b1 = ok1 ? __ldg(q2 + c1) : 0.f;
                sab[r][128 + tx] = pk2(a1, b1);
                sq [r][128 + tx] = pk2(fmaf(b1, b1, a1 * a1), a1 * b1);
            }
        }
        __syncthreads();

#pragma unroll
        for (int k = 0; k < 11; ++k) {
            // horizontal pass: 4 quantities
            float h0 = 0.f, h1 = 0.f, h2 = 0.f, h3 = 0.f;
#pragma unroll
            for (int i = 0; i < 11; ++i) {
                const float w = GWs[i];
                const float2 v = upk2(sab[k][tx + i]);
                const float2 q = upk2(sq [k][tx + i]);
                h0 = fmaf(w, v.x, h0);    // sum w*a
                h1 = fmaf(w, v.y, h1);    // sum w*b
                h2 = fmaf(w, q.x, h2);    // sum w*(a^2+b^2)
                h3 = fmaf(w, q.y, h3);    // sum w*(a*b)
            }
            r0[k] = h0; r1[k] = h1; r2[k] = h2; r3[k] = h3;

            const int n = t * 11 + k;
            if (n >= 10 && n < 74) {
                float m1 = 0.f, m2 = 0.f, spp = 0.f, s12 = 0.f;
#pragma unroll
                for (int j = 0; j < 11; ++j) {
                    const int s = (k + 1 + j) % 11;   // static after unroll
                    const float w = GWs[j];
                    m1  = fmaf(w, r0[s], m1);
                    m2  = fmaf(w, r1[s], m2);
                    spp = fmaf(w, r2[s], spp);
                    s12 = fmaf(w, r3[s], s12);
                }
                const float mu12  = m1 * m2;
                const float musq  = fmaf(m2, m2, m1 * m1);  // mu1^2 + mu2^2
                const float sig12 = s12 - mu12;
                const float sigpp = spp - musq;             // sigma1^2 + sigma2^2
                const float v1  = fmaf(2.f, sig12, C2);
                const float v2  = sigpp + C2E;
                const float num = fmaf(2.f, mu12, C1) * v1;
                const float den = (musq + C1) * v2;
                acc += __fdividef(num, den);
            }
        }
    }

#pragma unroll
    for (int o = 16; o > 0; o >>= 1)
        acc += __shfl_xor_sync(0xFFFFFFFFu, acc, o);

    __shared__ float wsum[4];
    if ((tx & 31) == 0) wsum[tx >> 5] = acc;
    __syncthreads();

    if (tx == 0) {
        const float s = wsum[0] + wsum[1] + wsum[2] + wsum[3];
        atomicAdd(&g_acc, (double)s);
        __threadfence();
        const unsigned int done = atomicAdd(&g_count, 1u);
        if (done == (unsigned)(N_BLOCKS - 1)) {
            const double total = atomicAdd(&g_acc, 0.0);
            out[0] = (float)(total / TOTAL_PIX);
            g_acc = 0.0;
            g_count = 0u;
            __threadfence();
        }
    }
}

extern "C" void kernel_launch(void* const* d_in, const int* in_sizes, int n_in,
                              void* d_out, int out_size) {
    const float* img1 = (const float*)d_in[0];
    const float* img2 = (const float*)d_in[1];
    float* out = (float*)d_out;
    (void)in_sizes; (void)n_in; (void)out_size;

    dim3 grid(N_PLANES, 4, 8);
    ssim_kernel<<<grid, 128>>>(img1, img2, out);
}

// round 5
// speedup vs baseline: 1.2686x; 1.2686x over previous
#include <cuda_runtime.h>

// ---------------------------------------------------------------------------
// SSIM (16,3,512,512) fp32, 11x11 gaussian (sigma=1.5), zero padding.
// Round-5:
//  * R3 packed-f32x2 horizontal (4 FMA-pipe instrs/tap, 1 LDS.64/tap) --
//    single smem array, crossbar-safe (R4's dual-array LDS killed it).
//  * ring compressed to 2 packed u64 per row slot: (sum wa, sum wb) and
//    (sum w(a^2+b^2), sum w*ab) -> 44 ring regs (was 55), vertical = 2
//    fma2 per tap (was 3).
//  * 32-row bands -> 3072 blocks (20.8 seq blocks/SM, smooth waves); the
//    R2/R3 grids capped occupancy at ~20 warps/SM (the real binder).
//  * __launch_bounds__(128, 7) -> target 7 blocks = 28 warps/SM.
// ---------------------------------------------------------------------------

#define IMG_H 512
#define IMG_W 512
#define N_PLANES 48
#define N_BLOCKS (48 * 4 * 16)
#define TOTAL_PIX 12582912.0

#define GW0 0.26601172f
#define GW1 0.21300554f
#define GW2 0.10936069f
#define GW3 0.03600077f
#define GW4 0.00759876f
#define GW5 0.00102842f

__device__ double g_acc;
__device__ unsigned int g_count;

typedef unsigned long long u64;

__device__ __forceinline__ u64 pk2(float lo, float hi) {
    u64 r; asm("mov.b64 %0, {%1, %2};" : "=l"(r) : "f"(lo), "f"(hi)); return r;
}
__device__ __forceinline__ float2 upk2(u64 v) {
    float2 r; asm("mov.b64 {%0, %1}, %2;" : "=f"(r.x), "=f"(r.y) : "l"(v)); return r;
}
__device__ __forceinline__ u64 fma2(u64 a, u64 b, u64 c) {
    u64 d; asm("fma.rn.f32x2 %0, %1, %2, %3;" : "=l"(d) : "l"(a), "l"(b), "l"(c)); return d;
}
__device__ __forceinline__ u64 mul2(u64 a, u64 b) {
    u64 d; asm("mul.rn.f32x2 %0, %1, %2;" : "=l"(d) : "l"(a), "l"(b)); return d;
}

__global__ __launch_bounds__(128, 7)
void ssim_kernel(const float* __restrict__ img1, const float* __restrict__ img2,
                 float* __restrict__ out) {
    const int WI[11] = {5, 4, 3, 2, 1, 0, 1, 2, 3, 4, 5};

    const int plane = blockIdx.x;     // 0..47
    const int strip = blockIdx.y;     // 0..3   (column strips of 128)
    const int band  = blockIdx.z;     // 0..15  (row bands of 32)
    const int tx    = threadIdx.x;    // 0..127

    const int col0 = strip * 128;
    const int row0 = band * 32;

    const float* __restrict__ p1 = img1 + (size_t)plane * (IMG_H * IMG_W);
    const float* __restrict__ p2 = img2 + (size_t)plane * (IMG_H * IMG_W);

    // interleaved (a,b) pairs: one u64 per column
    __shared__ u64 sab[11][140];

    u64 W2[6];
    W2[0] = pk2(GW0, GW0); W2[1] = pk2(GW1, GW1); W2[2] = pk2(GW2, GW2);
    W2[3] = pk2(GW3, GW3); W2[4] = pk2(GW4, GW4); W2[5] = pk2(GW5, GW5);

    // ring per row slot: ring01 = (sum wa, sum wb); ringq = (sum w(a^2+b^2), sum w*ab)
    u64 ring01[11], ringq[11];
#pragma unroll
    for (int k = 0; k < 11; ++k) { ring01[k] = 0ull; ringq[k] = 0ull; }

    float acc = 0.f;

    const float C1  = 1e-4f;
    const float C2  = 9e-4f;
    const float C2E = 9e-4f + 1e-6f;

    const int c0 = col0 - 5 + tx;
    const bool colok0 = ((unsigned)c0 < (unsigned)IMG_W);
    const int c1 = c0 + 128;
    const bool colok1 = ((unsigned)c1 < (unsigned)IMG_W);

    // input rows y = row0 - 5 + n, n = t*11 + k (44 n's, 42 real);
    // output emitted for n in [10, 42)
    for (int t = 0; t < 4; ++t) {
        const int base = row0 - 5 + t * 11;

        __syncthreads();
#pragma unroll
        for (int r = 0; r < 11; ++r) {
            const int y = base + r;
            const bool rowok = ((unsigned)y < (unsigned)IMG_H);
            const float* q1 = p1 + y * IMG_W;
            const float* q2 = p2 + y * IMG_W;
            const bool ok0 = rowok && colok0;
            const float a = ok0 ? __ldg(q1 + c0) : 0.f;
            const float b = ok0 ? __ldg(q2 + c0) : 0.f;
            sab[r][tx] = pk2(a, b);
            if (tx < 11) {
                const bool ok1 = rowok && colok1;
                const float a1 = ok1 ? __ldg(q1 + c1) : 0.f;
                const float b1 = ok1 ? __ldg(q2 + c1) : 0.f;
                sab[r][128 + tx] = pk2(a1, b1);
            }
        }
        __syncthreads();

#pragma unroll
        for (int k = 0; k < 11; ++k) {
            const u64* srow = sab[k];
            u64 h01 = 0ull, h23 = 0ull;
            float h4 = 0.f;
#pragma unroll
            for (int i = 0; i < 11; ++i) {
                const u64 vv = srow[tx + i];          // LDS.64: (a,b)
                const u64 w  = W2[WI[i]];
                h01 = fma2(w, vv, h01);               // (+wa, +wb)
                const u64 p = mul2(w, vv);            // (wa, wb)
                h23 = fma2(p, vv, h23);               // (+wa^2, +wb^2)
                const float2 pf = upk2(p);
                const float2 vf = upk2(vv);
                h4 = fmaf(pf.x, vf.y, h4);            // +w*a*b
            }
            const float2 hq = upk2(h23);
            ring01[k] = h01;
            ringq [k] = pk2(hq.x + hq.y, h4);         // (spp-partial, s12-partial)

            const int n = t * 11 + k;
            if (n >= 10 && n < 42) {
                u64 m12 = 0ull, qv = 0ull;
#pragma unroll
                for (int j = 0; j < 11; ++j) {
                    const int s = (k + 1 + j) % 11;   // static after unroll
                    const u64 w = W2[WI[j]];
                    m12 = fma2(w, ring01[s], m12);
                    qv  = fma2(w, ringq [s], qv);
                }
                const float2 m = upk2(m12);           // (mu1, mu2)
                const float2 q = upk2(qv);            // (spp, s12)
                const float mu12  = m.x * m.y;
                const float musq  = fmaf(m.y, m.y, m.x * m.x);
                const float sig12 = q.y - mu12;
                const float sigpp = q.x - musq;
                const float v1  = fmaf(2.f, sig12, C2);
                const float v2  = sigpp + C2E;
                const float num = fmaf(2.f, mu12, C1) * v1;
                const float den = (musq + C1) * v2;
                acc += __fdividef(num, den);
            }
        }
    }

#pragma unroll
    for (int o = 16; o > 0; o >>= 1)
        acc += __shfl_xor_sync(0xFFFFFFFFu, acc, o);

    __shared__ float wsum[4];
    if ((tx & 31) == 0) wsum[tx >> 5] = acc;
    __syncthreads();

    if (tx == 0) {
        const float s = wsum[0] + wsum[1] + wsum[2] + wsum[3];
        atomicAdd(&g_acc, (double)s);
        __threadfence();
        const unsigned int done = atomicAdd(&g_count, 1u);
        if (done == (unsigned)(N_BLOCKS - 1)) {
            const double total = atomicAdd(&g_acc, 0.0);
            out[0] = (float)(total / TOTAL_PIX);
            g_acc = 0.0;
            g_count = 0u;
            __threadfence();
        }
    }
}

extern "C" void kernel_launch(void* const* d_in, const int* in_sizes, int n_in,
                              void* d_out, int out_size) {
    const float* img1 = (const float*)d_in[0];
    const float* img2 = (const float*)d_in[1];
    float* out = (float*)d_out;
    (void)in_sizes; (void)n_in; (void)out_size;

    dim3 grid(N_PLANES, 4, 16);
    ssim_kernel<<<grid, 128>>>(img1, img2, out);
}

// round 6
// speedup vs baseline: 1.8794x; 1.4815x over previous
#include <cuda_runtime.h>

// ---------------------------------------------------------------------------
// SSIM (16,3,512,512) fp32, 11x11 gaussian (sigma=1.5), zero padding.
// Round-6:
//  * cp.async (LDGSTS) double-buffered smem loads with zfill for padding --
//    removes the per-chunk DRAM-latency barrier stall (R5: issue 42.5% at
//    occ 39% = warps stalled on LDG under barrier).
//  * planar smem (a,b separate), pack to f32x2 in registers; packed math
//    as in R5 (88 fma-cyc horizontal + 44 vertical per output row).
//  * 64-row bands (grid 1536): horizontal waste 1.375x -> 1.20x.
// ---------------------------------------------------------------------------

#define IMG_H 512
#define IMG_W 512
#define N_PLANES 48
#define N_BLOCKS (48 * 4 * 8)
#define TOTAL_PIX 12582912.0

#define GW0 0.26601172f
#define GW1 0.21300554f
#define GW2 0.10936069f
#define GW3 0.03600077f
#define GW4 0.00759876f
#define GW5 0.00102842f

__device__ double g_acc;
__device__ unsigned int g_count;

typedef unsigned long long u64;

__device__ __forceinline__ u64 pk2(float lo, float hi) {
    u64 r; asm("mov.b64 %0, {%1, %2};" : "=l"(r) : "f"(lo), "f"(hi)); return r;
}
__device__ __forceinline__ float2 upk2(u64 v) {
    float2 r; asm("mov.b64 {%0, %1}, %2;" : "=f"(r.x), "=f"(r.y) : "l"(v)); return r;
}
__device__ __forceinline__ u64 fma2(u64 a, u64 b, u64 c) {
    u64 d; asm("fma.rn.f32x2 %0, %1, %2, %3;" : "=l"(d) : "l"(a), "l"(b), "l"(c)); return d;
}
__device__ __forceinline__ u64 mul2(u64 a, u64 b) {
    u64 d; asm("mul.rn.f32x2 %0, %1, %2;" : "=l"(d) : "l"(a), "l"(b)); return d;
}
__device__ __forceinline__ void cp16(unsigned dst, const void* src, unsigned rs) {
    asm volatile("cp.async.cg.shared.global [%0], [%1], 16, %2;"
                 :: "r"(dst), "l"(src), "r"(rs));
}

// smem row: 148 floats, covering global cols [col0-8, col0+140)
// window for thread tx: smem idx tx+3 .. tx+13
#define RW 148
#define NCP 37                    // 16B chunks per row per array
#define CHUNK_COPIES (11 * 2 * NCP)   // 814

__global__ __launch_bounds__(128, 7)
void ssim_kernel(const float* __restrict__ img1, const float* __restrict__ img2,
                 float* __restrict__ out) {
    const int WI[11] = {5, 4, 3, 2, 1, 0, 1, 2, 3, 4, 5};

    const int plane = blockIdx.x;     // 0..47
    const int strip = blockIdx.y;     // 0..3   (column strips of 128)
    const int band  = blockIdx.z;     // 0..7   (row bands of 64)
    const int tx    = threadIdx.x;

    const int col0 = strip * 128;
    const int row0 = band * 64;

    const float* __restrict__ p1 = img1 + (size_t)plane * (IMG_H * IMG_W);
    const float* __restrict__ p2 = img2 + (size_t)plane * (IMG_H * IMG_W);

    // [buf][row][array(a/b)][col]
    __shared__ __align__(16) float smem[2][11][2][RW];

    unsigned sbase;
    asm("{ .reg .u64 t; cvta.to.shared.u64 t, %1; cvt.u32.u64 %0, t; }"
        : "=r"(sbase) : "l"((const void*)smem));

    u64 W2[6];
    W2[0] = pk2(GW0, GW0); W2[1] = pk2(GW1, GW1); W2[2] = pk2(GW2, GW2);
    W2[3] = pk2(GW3, GW3); W2[4] = pk2(GW4, GW4); W2[5] = pk2(GW5, GW5);

    u64 ring01[11], ringq[11];
#pragma unroll
    for (int k = 0; k < 11; ++k) { ring01[k] = 0ull; ringq[k] = 0ull; }

    float acc = 0.f;
    const float C1  = 1e-4f;
    const float C2  = 9e-4f;
    const float C2E = 9e-4f + 1e-6f;

    // ---- async chunk loader: 11 rows (a and b) into buffer bb ----
    auto load_chunk = [&](int t, int bb) {
        const int base = row0 - 5 + t * 11;
#pragma unroll 1
        for (int j = tx; j < CHUNK_COPIES; j += 128) {
            const int row = j / (2 * NCP);
            const int rem = j - row * (2 * NCP);
            const int arr = (rem >= NCP) ? 1 : 0;
            const int pos = rem - arr * NCP;
            const int y = base + row;
            const int gcol = col0 - 8 + pos * 4;
            const bool ok = ((unsigned)y < (unsigned)IMG_H) &&
                            ((unsigned)gcol < (unsigned)IMG_W);
            const float* src = (arr ? p2 : p1) + (ok ? (y * IMG_W + gcol) : 0);
            const unsigned rs = ok ? 16u : 0u;
            const unsigned dst = sbase +
                (unsigned)((((bb * 11 + row) * 2 + arr) * RW + pos * 4) * 4);
            cp16(dst, src, rs);
        }
        asm volatile("cp.async.commit_group;");
    };

    // prologue: chunk 0 into buf 0
    load_chunk(0, 0);

    // input rows n = t*11 + k, 7 chunks (77 slots, rows 0..76); outputs n in [10,74)
    for (int t = 0; t < 7; ++t) {
        const int cur = t & 1;
        if (t < 6) load_chunk(t + 1, cur ^ 1);

        if (t < 6) asm volatile("cp.async.wait_group 1;");
        else       asm volatile("cp.async.wait_group 0;");
        __syncthreads();   // chunk t visible to all

#pragma unroll
        for (int k = 0; k < 11; ++k) {
            const float* sa = smem[cur][k][0];
            const float* sb = smem[cur][k][1];
            u64 h01 = 0ull, h23 = 0ull;
            float h4 = 0.f;
#pragma unroll
            for (int i = 0; i < 11; ++i) {
                const float a = sa[tx + 3 + i];
                const float b = sb[tx + 3 + i];
                const u64 vv = pk2(a, b);
                const u64 w  = W2[WI[i]];
                h01 = fma2(w, vv, h01);               // (+wa, +wb)
                const u64 p = mul2(w, vv);            // (wa, wb)
                h23 = fma2(p, vv, h23);               // (+wa^2, +wb^2)
                const float2 pf = upk2(p);
                h4 = fmaf(pf.x, b, h4);               // +w*a*b
            }
            const float2 hq = upk2(h23);
            ring01[k] = h01;
            ringq [k] = pk2(hq.x + hq.y, h4);

            const int n = t * 11 + k;
            if (n >= 10 && n < 74) {
                u64 m12 = 0ull, qv = 0ull;
#pragma unroll
                for (int j = 0; j < 11; ++j) {
                    const int s = (k + 1 + j) % 11;   // static after unroll
                    const u64 w = W2[WI[j]];
                    m12 = fma2(w, ring01[s], m12);
                    qv  = fma2(w, ringq [s], qv);
                }
                const float2 m = upk2(m12);           // (mu1, mu2)
                const float2 q = upk2(qv);            // (spp, s12)
                const float mu12  = m.x * m.y;
                const float musq  = fmaf(m.y, m.y, m.x * m.x);
                const float sig12 = q.y - mu12;
                const float sigpp = q.x - musq;
                const float v1  = fmaf(2.f, sig12, C2);
                const float v2  = sigpp + C2E;
                const float num = fmaf(2.f, mu12, C1) * v1;
                const float den = (musq + C1) * v2;
                acc += __fdividef(num, den);
            }
        }
        __syncthreads();   // buffer cur free for chunk t+2's loads
    }

#pragma unroll
    for (int o = 16; o > 0; o >>= 1)
        acc += __shfl_xor_sync(0xFFFFFFFFu, acc, o);

    __shared__ float wsum[4];
    if ((tx & 31) == 0) wsum[tx >> 5] = acc;
    __syncthreads();

    if (tx == 0) {
        const float s = wsum[0] + wsum[1] + wsum[2] + wsum[3];
        atomicAdd(&g_acc, (double)s);
        __threadfence();
        const unsigned int done = atomicAdd(&g_count, 1u);
        if (done == (unsigned)(N_BLOCKS - 1)) {
            const double total = atomicAdd(&g_acc, 0.0);
            out[0] = (float)(total / TOTAL_PIX);
            g_acc = 0.0;
            g_count = 0u;
            __threadfence();
        }
    }
}

extern "C" void kernel_launch(void* const* d_in, const int* in_sizes, int n_in,
                              void* d_out, int out_size) {
    const float* img1 = (const float*)d_in[0];
    const float* img2 = (const float*)d_in[1];
    float* out = (float*)d_out;
    (void)in_sizes; (void)n_in; (void)out_size;

    dim3 grid(N_PLANES, 4, 8);
    ssim_kernel<<<grid, 128>>>(img1, img2, out);
}

// round 7
// speedup vs baseline: 1.9529x; 1.0391x over previous
#include <cuda_runtime.h>

// ---------------------------------------------------------------------------
// SSIM (16,3,512,512) fp32, 11x11 gaussian (sigma=1.5), zero padding.
// Round-7 (base: R6 cp.async double-buffered, packed f32x2 math, 87.6us):
//  * 32-row bands -> 3072 blocks: R6's 1536 big blocks ran ~1.5 resident
//    generations -> ~25% tail idle (achieved occ 33.7% vs 58% theoretical).
//    3 generations of half-size blocks cuts tail to ~2%.
//  * loader: fixed (array, chunk-column) per thread (tx<74), row-loop inside;
//    all column/address math hoisted out of the hot path (~12 -> ~4 ops per
//    cp.async; alu pipe was 19%).
// ---------------------------------------------------------------------------

#define IMG_H 512
#define IMG_W 512
#define N_PLANES 48
#define N_BLOCKS (48 * 4 * 16)
#define TOTAL_PIX 12582912.0

#define GW0 0.26601172f
#define GW1 0.21300554f
#define GW2 0.10936069f
#define GW3 0.03600077f
#define GW4 0.00759876f
#define GW5 0.00102842f

__device__ double g_acc;
__device__ unsigned int g_count;

typedef unsigned long long u64;

__device__ __forceinline__ u64 pk2(float lo, float hi) {
    u64 r; asm("mov.b64 %0, {%1, %2};" : "=l"(r) : "f"(lo), "f"(hi)); return r;
}
__device__ __forceinline__ float2 upk2(u64 v) {
    float2 r; asm("mov.b64 {%0, %1}, %2;" : "=f"(r.x), "=f"(r.y) : "l"(v)); return r;
}
__device__ __forceinline__ u64 fma2(u64 a, u64 b, u64 c) {
    u64 d; asm("fma.rn.f32x2 %0, %1, %2, %3;" : "=l"(d) : "l"(a), "l"(b), "l"(c)); return d;
}
__device__ __forceinline__ u64 mul2(u64 a, u64 b) {
    u64 d; asm("mul.rn.f32x2 %0, %1, %2;" : "=l"(d) : "l"(a), "l"(b)); return d;
}
__device__ __forceinline__ void cp16(unsigned dst, const void* src, unsigned rs) {
    asm volatile("cp.async.cg.shared.global [%0], [%1], 16, %2;"
                 :: "r"(dst), "l"(src), "r"(rs));
}

// smem row: 148 floats, covering global cols [col0-8, col0+140)
// thread tx's 11-tap window: smem idx tx+3 .. tx+13
#define RW 148
#define ROW_STRIDE_B (2 * RW * 4)        // 1184 bytes (row of a + row of b)
#define BUF_STRIDE_B (11 * 2 * RW * 4)   // 13024 bytes

__global__ __launch_bounds__(128, 7)
void ssim_kernel(const float* __restrict__ img1, const float* __restrict__ img2,
                 float* __restrict__ out) {
    const int WI[11] = {5, 4, 3, 2, 1, 0, 1, 2, 3, 4, 5};

    const int plane = blockIdx.x;     // 0..47
    const int strip = blockIdx.y;     // 0..3   (column strips of 128)
    const int band  = blockIdx.z;     // 0..15  (row bands of 32)
    const int tx    = threadIdx.x;

    const int col0 = strip * 128;
    const int row0 = band * 32;

    const float* __restrict__ p1 = img1 + (size_t)plane * (IMG_H * IMG_W);
    const float* __restrict__ p2 = img2 + (size_t)plane * (IMG_H * IMG_W);

    // [buf][row][array(a/b)][col]
    __shared__ __align__(16) float smem[2][11][2][RW];

    unsigned sbase;
    asm("{ .reg .u64 t; cvta.to.shared.u64 t, %1; cvt.u32.u64 %0, t; }"
        : "=r"(sbase) : "l"((const void*)smem));

    // ---- loader constants: thread tx<74 owns one 16B chunk column ----
    const int  larr  = (tx >= 37) ? 1 : 0;
    const int  lpos  = tx - 37 * larr;               // 0..36
    const int  lgcol = col0 - 8 + lpos * 4;
    const bool lcolok = (tx < 74) && ((unsigned)lgcol < (unsigned)IMG_W);
    const float* lsrc = (larr ? p2 : p1) + lgcol;
    const unsigned ldst = sbase + (unsigned)((larr * RW + lpos * 4) * 4);

    u64 W2[6];
    W2[0] = pk2(GW0, GW0); W2[1] = pk2(GW1, GW1); W2[2] = pk2(GW2, GW2);
    W2[3] = pk2(GW3, GW3); W2[4] = pk2(GW4, GW4); W2[5] = pk2(GW5, GW5);

    u64 ring01[11], ringq[11];
#pragma unroll
    for (int k = 0; k < 11; ++k) { ring01[k] = 0ull; ringq[k] = 0ull; }

    float acc = 0.f;
    const float C1  = 1e-4f;
    const float C2  = 9e-4f;
    const float C2E = 9e-4f + 1e-6f;

    // ---- async chunk loader: 11 rows (a and b) into buffer bb ----
    auto load_chunk = [&](int t, int bb) {
        if (tx < 74) {
            const int base = row0 - 5 + t * 11;
            const unsigned dbase = ldst + (unsigned)(bb * BUF_STRIDE_B);
#pragma unroll
            for (int r = 0; r < 11; ++r) {
                const int y = base + r;
                const bool ok = lcolok && ((unsigned)y < (unsigned)IMG_H);
                const float* src = ok ? (lsrc + y * IMG_W) : p1;
                cp16(dbase + (unsigned)(r * ROW_STRIDE_B), src, ok ? 16u : 0u);
            }
        }
        asm volatile("cp.async.commit_group;");
    };

    load_chunk(0, 0);

    // input rows n = t*11 + k, 4 chunks (44 slots, rows 0..43);
    // outputs emitted for n in [10, 42)
    for (int t = 0; t < 4; ++t) {
        const int cur = t & 1;
        if (t < 3) {
            load_chunk(t + 1, cur ^ 1);
            asm volatile("cp.async.wait_group 1;");
        } else {
            asm volatile("cp.async.wait_group 0;");
        }
        __syncthreads();   // chunk t visible to all

#pragma unroll
        for (int k = 0; k < 11; ++k) {
            const float* sa = smem[cur][k][0];
            const float* sb = smem[cur][k][1];
            u64 h01 = 0ull, h23 = 0ull;
            float h4 = 0.f;
#pragma unroll
            for (int i = 0; i < 11; ++i) {
                const float a = sa[tx + 3 + i];
                const float b = sb[tx + 3 + i];
                const u64 vv = pk2(a, b);
                const u64 w  = W2[WI[i]];
                h01 = fma2(w, vv, h01);               // (+wa, +wb)
                const u64 p = mul2(w, vv);            // (wa, wb)
                h23 = fma2(p, vv, h23);               // (+wa^2, +wb^2)
                const float2 pf = upk2(p);
                h4 = fmaf(pf.x, b, h4);               // +w*a*b
            }
            const float2 hq = upk2(h23);
            ring01[k] = h01;
            ringq [k] = pk2(hq.x + hq.y, h4);

            const int n = t * 11 + k;
            if (n >= 10 && n < 42) {
                u64 m12 = 0ull, qv = 0ull;
#pragma unroll
                for (int j = 0; j < 11; ++j) {
                    const int s = (k + 1 + j) % 11;   // static after unroll
                    const u64 w = W2[WI[j]];
                    m12 = fma2(w, ring01[s], m12);
                    qv  = fma2(w, ringq [s], qv);
                }
                const float2 m = upk2(m12);           // (mu1, mu2)
                const float2 q = upk2(qv);            // (spp, s12)
                const float mu12  = m.x * m.y;
                const float musq  = fmaf(m.y, m.y, m.x * m.x);
                const float sig12 = q.y - mu12;
                const float sigpp = q.x - musq;
                const float v1  = fmaf(2.f, sig12, C2);
                const float v2  = sigpp + C2E;
                const float num = fmaf(2.f, mu12, C1) * v1;
                const float den = (musq + C1) * v2;
                acc += __fdividef(num, den);
            }
        }
        __syncthreads();   // buffer cur free for chunk t+2's loads
    }

#pragma unroll
    for (int o = 16; o > 0; o >>= 1)
        acc += __shfl_xor_sync(0xFFFFFFFFu, acc, o);

    __shared__ float wsum[4];
    if ((tx & 31) == 0) wsum[tx >> 5] = acc;
    __syncthreads();

    if (tx == 0) {
        const float s = wsum[0] + wsum[1] + wsum[2] + wsum[3];
        atomicAdd(&g_acc, (double)s);
        __threadfence();
        const unsigned int done = atomicAdd(&g_count, 1u);
        if (done == (unsigned)(N_BLOCKS - 1)) {
            const double total = atomicAdd(&g_acc, 0.0);
            out[0] = (float)(total / TOTAL_PIX);
            g_acc = 0.0;
            g_count = 0u;
            __threadfence();
        }
    }
}

extern "C" void kernel_launch(void* const* d_in, const int* in_sizes, int n_in,
                              void* d_out, int out_size) {
    const float* img1 = (const float*)d_in[0];
    const float* img2 = (const float*)d_in[1];
    float* out = (float*)d_out;
    (void)in_sizes; (void)n_in; (void)out_size;

    dim3 grid(N_PLANES, 4, 16);
    ssim_kernel<<<grid, 128>>>(img1, img2, out);
}